// round 14
// baseline (speedup 1.0000x reference)
#include <cuda_runtime.h>

// Problem constants (match reference_code)
#define NU    30000
#define NENT  70000
#define NN    100000          // NU + NENT
#define NEDGE 1600000
#define NB    4096

#define SCAN_ELEMS 512
#define NBLK_SCAN  ((NN + SCAN_ELEMS - 1) / SCAN_ELEMS)   // 196

// Scratch (device globals: allocation-free rule).
__device__ float g_feats0[NN * 64];
__device__ float g_a1[NN * 64];
__device__ float g_a2[NN * 32];
// CSR scratch
__device__ int   g_cnt[NN];
__device__ int   g_rowptr[NN + 1];
__device__ int   g_cursor[NN];
__device__ int   g_bsum[256];
__device__ int   g_boff[256];
__device__ int2  g_ecv[NEDGE];       // x = col, y = float bits of val

// ---------------------------------------------------------------------------
// K0: a0 = concat(user_embed, entity_embed) (float4 copy) + zero CSR counters
// ---------------------------------------------------------------------------
__global__ __launch_bounds__(256) void concat_kernel(
    const float* __restrict__ ue, const float* __restrict__ ee)
{
    int idx = blockIdx.x * 256 + threadIdx.x;           // over NN*16 float4
    if (idx < NN) g_cnt[idx] = 0;
    if (idx >= NN * 16) return;
    float4 v = (idx < NU * 16) ? ((const float4*)ue)[idx]
                               : ((const float4*)ee)[idx - NU * 16];
    ((float4*)g_feats0)[idx] = v;
}

// ---------------------------------------------------------------------------
// CSR build: histogram -> 3-phase exclusive scan -> fill
// ---------------------------------------------------------------------------
__global__ __launch_bounds__(256) void hist_kernel(const int* __restrict__ er)
{
    int e = blockIdx.x * 256 + threadIdx.x;
    if (e < NEDGE) atomicAdd(&g_cnt[er[e]], 1);
}

__global__ __launch_bounds__(SCAN_ELEMS) void scan1_kernel()
{
    __shared__ int s[SCAN_ELEMS];
    int i = blockIdx.x * SCAN_ELEMS + threadIdx.x;
    int v = (i < NN) ? g_cnt[i] : 0;
    s[threadIdx.x] = v;
    __syncthreads();
    #pragma unroll
    for (int off = 1; off < SCAN_ELEMS; off <<= 1) {
        int t = (threadIdx.x >= off) ? s[threadIdx.x - off] : 0;
        __syncthreads();
        s[threadIdx.x] += t;
        __syncthreads();
    }
    if (i < NN) g_rowptr[i] = s[threadIdx.x] - v;        // exclusive within block
    if (threadIdx.x == SCAN_ELEMS - 1) g_bsum[blockIdx.x] = s[SCAN_ELEMS - 1];
}

__global__ __launch_bounds__(256) void scan2_kernel()
{
    __shared__ int s[256];
    int v = (threadIdx.x < NBLK_SCAN) ? g_bsum[threadIdx.x] : 0;
    s[threadIdx.x] = v;
    __syncthreads();
    #pragma unroll
    for (int off = 1; off < 256; off <<= 1) {
        int t = (threadIdx.x >= off) ? s[threadIdx.x - off] : 0;
        __syncthreads();
        s[threadIdx.x] += t;
        __syncthreads();
    }
    g_boff[threadIdx.x] = s[threadIdx.x] - v;            // exclusive
}

__global__ __launch_bounds__(256) void scan3_kernel()
{
    int i = blockIdx.x * 256 + threadIdx.x;
    if (i < NN) {
        int rp = g_rowptr[i] + g_boff[i / SCAN_ELEMS];
        g_rowptr[i] = rp;
        g_cursor[i] = rp;
    }
    if (i == 0) g_rowptr[NN] = NEDGE;
}

__global__ __launch_bounds__(256) void fill_kernel(
    const int* __restrict__ er, const int* __restrict__ ec,
    const float* __restrict__ ev)
{
    int e = blockIdx.x * 256 + threadIdx.x;
    if (e >= NEDGE) return;
    int row = er[e];
    int pos = atomicAdd(&g_cursor[row], 1);
    g_ecv[pos] = make_int2(ec[e], __float_as_int(ev[e]));
}

// ---------------------------------------------------------------------------
// Fused layer kernel: pull-mode SpMM gather into shared Xs/Ys, then dense
// GEMM + leaky_relu + L2 normalize.
// Block = 64 rows, 512 threads (16 warps, warp handles 4 rows), 3 CTAs/SM.
// Gather: lane-parallel edge staging (one coalesced LDG.64 per 32 edges)
// + shfl broadcast; feature loads issue from register addresses.
// Lane covers feature cols {lane, lane+32} -> two 128B-line LDG.32 per edge.
// ---------------------------------------------------------------------------
template<int DOUT, int LAYER>
__global__ __launch_bounds__(512, 3) void layer_fused_kernel(
    const float* __restrict__ W1, const float* __restrict__ b1,
    const float* __restrict__ W2, const float* __restrict__ b2)
{
    const float* __restrict__ feats = (LAYER == 0) ? g_feats0 : g_a1;
    float*       out                = (LAYER == 0) ? g_a1     : g_a2;

    extern __shared__ float sm[];
    float* Xs  = sm;                    // [64][65], k-major: Xs[k*65 + node]
    float* Ys  = Xs + 64 * 65;          // [64][65]
    float* W1s = Ys + 64 * 65;          // [64*DOUT]
    float* W2s = W1s + 64 * DOUT;       // [64*DOUT]
    float* Bs  = W2s + 64 * DOUT;       // [DOUT]

    const int tid  = threadIdx.x;
    const int r0   = blockIdx.x * 64;
    const int warp = tid >> 5;
    const int lane = tid & 31;

    // ---- stage W (float4) and bias sum ----
    for (int idx = tid; idx < 64 * DOUT / 4; idx += 512) {
        ((float4*)W1s)[idx] = ((const float4*)W1)[idx];
        ((float4*)W2s)[idx] = ((const float4*)W2)[idx];
    }
    if (tid < DOUT) Bs[tid] = b1[tid] + b2[tid];

    // ---- pull-mode gather: lane-staged edges + shfl broadcast ----
    #pragma unroll 1
    for (int i = 0; i < 4; i++) {
        int rl = warp * 4 + i;
        int gr = r0 + rl;
        float f0 = 0.f, f1 = 0.f, h0 = 0.f, h1 = 0.f;
        if (gr < NN) {
            f0 = feats[gr * 64 + lane];
            f1 = feats[gr * 64 + 32 + lane];
            int beg = g_rowptr[gr];
            int end = g_rowptr[gr + 1];
            for (int base = beg; base < end; base += 32) {
                // one coalesced load: each lane stages one edge record
                int2 cv = make_int2(0, 0);
                if (base + lane < end) cv = g_ecv[base + lane];
                int n = min(32, end - base);
                #pragma unroll 4
                for (int j = 0; j < n; j++) {
                    int   col = __shfl_sync(0xFFFFFFFFu, cv.x, j);
                    float v   = __int_as_float(__shfl_sync(0xFFFFFFFFu, cv.y, j));
                    const float* fp = feats + (size_t)col * 64;
                    h0 += fp[lane] * v;
                    h1 += fp[32 + lane] * v;
                }
            }
        }
        Xs[lane * 65 + rl]        = f0 + h0;
        Xs[(lane + 32) * 65 + rl] = f1 + h1;
        Ys[lane * 65 + rl]        = f0 * h0;
        Ys[(lane + 32) * 65 + rl] = f1 * h1;
    }
    __syncthreads();

    // ---- dense GEMM: thread (tx,ty) -> 2 nodes x JT outputs ----
    constexpr int JT = DOUT / 16;       // 4 (layer0) or 2 (layer1)
    const int tx = tid & 15;
    const int ty = tid >> 4;            // 0..31

    float acc[2][JT];
    #pragma unroll
    for (int i = 0; i < 2; i++)
        #pragma unroll
        for (int j = 0; j < JT; j++)
            acc[i][j] = Bs[tx * JT + j];

    for (int k = 0; k < 64; k++) {
        float x[2], y[2];
        #pragma unroll
        for (int i = 0; i < 2; i++) {
            x[i] = Xs[k * 65 + ty * 2 + i];
            y[i] = Ys[k * 65 + ty * 2 + i];
        }
        float w1[JT], w2[JT];
        if constexpr (JT == 4) {
            float4 a = *(const float4*)&W1s[k * DOUT + tx * 4];
            float4 b = *(const float4*)&W2s[k * DOUT + tx * 4];
            w1[0] = a.x; w1[1] = a.y; w1[2] = a.z; w1[3] = a.w;
            w2[0] = b.x; w2[1] = b.y; w2[2] = b.z; w2[3] = b.w;
        } else {
            float2 a = *(const float2*)&W1s[k * DOUT + tx * 2];
            float2 b = *(const float2*)&W2s[k * DOUT + tx * 2];
            w1[0] = a.x; w1[1] = a.y;
            w2[0] = b.x; w2[1] = b.y;
        }
        #pragma unroll
        for (int i = 0; i < 2; i++)
            #pragma unroll
            for (int j = 0; j < JT; j++)
                acc[i][j] += x[i] * w1[j] + y[i] * w2[j];
    }

    // ---- epilogue: leaky_relu + L2 normalize (width-16 shfl reduction) ----
    #pragma unroll
    for (int i = 0; i < 2; i++) {
        float p = 0.f;
        #pragma unroll
        for (int j = 0; j < JT; j++) {
            float v = acc[i][j];
            v = (v > 0.f) ? v : 0.01f * v;
            acc[i][j] = v;
            p += v * v;
        }
        p += __shfl_xor_sync(0xFFFFFFFFu, p, 1, 16);
        p += __shfl_xor_sync(0xFFFFFFFFu, p, 2, 16);
        p += __shfl_xor_sync(0xFFFFFFFFu, p, 4, 16);
        p += __shfl_xor_sync(0xFFFFFFFFu, p, 8, 16);
        float inv = 1.f / fmaxf(sqrtf(p), 1e-12f);
        int gr = r0 + ty * 2 + i;
        if (gr < NN) {
            if constexpr (JT == 4) {
                float4 o = make_float4(acc[i][0] * inv, acc[i][1] * inv,
                                       acc[i][2] * inv, acc[i][3] * inv);
                ((float4*)out)[gr * (DOUT / 4) + tx] = o;
            } else {
                float2 o = make_float2(acc[i][0] * inv, acc[i][1] * inv);
                ((float2*)out)[gr * (DOUT / 2) + tx] = o;
            }
        }
    }
}

// ---------------------------------------------------------------------------
// Scoring — warp per pair, dot over concat(a0[64], a1[64], a2[32]).
// ---------------------------------------------------------------------------
__global__ __launch_bounds__(256) void score_kernel(
    const int* __restrict__ uids, const int* __restrict__ iids,
    float* __restrict__ out)
{
    int w = (blockIdx.x * 256 + threadIdx.x) >> 5;
    int l = threadIdx.x & 31;
    if (w >= NB) return;
    int u  = uids[w];
    int it = NU + iids[w];

    const float* fu = g_feats0 + u  * 64;
    const float* fi = g_feats0 + it * 64;
    float s = fu[l] * fi[l] + fu[l + 32] * fi[l + 32];
    const float* au = g_a1 + u  * 64;
    const float* ai = g_a1 + it * 64;
    s += au[l] * ai[l] + au[l + 32] * ai[l + 32];
    s += g_a2[u * 32 + l] * g_a2[it * 32 + l];

    s += __shfl_xor_sync(0xFFFFFFFFu, s, 16);
    s += __shfl_xor_sync(0xFFFFFFFFu, s, 8);
    s += __shfl_xor_sync(0xFFFFFFFFu, s, 4);
    s += __shfl_xor_sync(0xFFFFFFFFu, s, 2);
    s += __shfl_xor_sync(0xFFFFFFFFu, s, 1);
    if (l == 0) out[w] = s;
}

// ---------------------------------------------------------------------------
extern "C" void kernel_launch(void* const* d_in, const int* in_sizes, int n_in,
                              void* d_out, int out_size)
{
    const int*   er   = (const int*)  d_in[0];
    const int*   ec   = (const int*)  d_in[1];
    const float* ev   = (const float*)d_in[2];
    const float* ue   = (const float*)d_in[3];
    const float* ee   = (const float*)d_in[4];
    const float* W1_0 = (const float*)d_in[5];
    const float* b1_0 = (const float*)d_in[6];
    const float* W2_0 = (const float*)d_in[7];
    const float* b2_0 = (const float*)d_in[8];
    const float* W1_1 = (const float*)d_in[9];
    const float* b1_1 = (const float*)d_in[10];
    const float* W2_1 = (const float*)d_in[11];
    const float* b2_1 = (const float*)d_in[12];
    const int*   uids = (const int*)  d_in[13];
    const int*   iids = (const int*)  d_in[14];
    float*       out  = (float*)d_out;

    const size_t smem64 = (size_t)(64 * 65 * 2 + 64 * 64 * 2 + 64) * sizeof(float);
    const size_t smem32 = (size_t)(64 * 65 * 2 + 64 * 32 * 2 + 32) * sizeof(float);
    cudaFuncSetAttribute(layer_fused_kernel<64, 0>,
                         cudaFuncAttributeMaxDynamicSharedMemorySize, (int)smem64);
    cudaFuncSetAttribute(layer_fused_kernel<32, 1>,
                         cudaFuncAttributeMaxDynamicSharedMemorySize, (int)smem32);

    const int layer_blocks = (NN + 63) / 64;
    const int eblocks = (NEDGE + 255) / 256;

    concat_kernel<<<(NN * 16 + 255) / 256, 256>>>(ue, ee);   // also zeros g_cnt
    // CSR build
    hist_kernel<<<eblocks, 256>>>(er);
    scan1_kernel<<<NBLK_SCAN, SCAN_ELEMS>>>();
    scan2_kernel<<<1, 256>>>();
    scan3_kernel<<<(NN + 255) / 256, 256>>>();
    fill_kernel<<<eblocks, 256>>>(er, ec, ev);
    // Fused layers
    layer_fused_kernel<64, 0><<<layer_blocks, 512, smem64>>>(W1_0, b1_0, W2_0, b2_0);
    layer_fused_kernel<32, 1><<<layer_blocks, 512, smem32>>>(W1_1, b1_1, W2_1, b2_1);
    score_kernel<<<(NB * 32) / 256, 256>>>(uids, iids, out);
}

// round 15
// speedup vs baseline: 1.0100x; 1.0100x over previous
#include <cuda_runtime.h>

// Problem constants (match reference_code)
#define NU    30000
#define NENT  70000
#define NN    100000          // NU + NENT
#define NEDGE 1600000
#define NB    4096

#define SCAN_ELEMS 512
#define NBLK_SCAN  ((NN + SCAN_ELEMS - 1) / SCAN_ELEMS)   // 196

// Scratch (device globals: allocation-free rule).
__device__ float g_feats0[NN * 64];
__device__ float g_a1[NN * 64];
__device__ float g_a2[NN * 32];
// CSR scratch
__device__ int   g_cnt[NN];
__device__ int   g_rowptr[NN + 1];
__device__ int   g_cursor[NN];
__device__ int   g_bsum[256];
__device__ int   g_boff[256];
__device__ int2  g_ecv[NEDGE];       // x = col, y = float bits of val

// ---------------------------------------------------------------------------
// K0: a0 = concat(user_embed, entity_embed) (float4 copy) + zero CSR counters
// ---------------------------------------------------------------------------
__global__ __launch_bounds__(256) void concat_kernel(
    const float* __restrict__ ue, const float* __restrict__ ee)
{
    int idx = blockIdx.x * 256 + threadIdx.x;           // over NN*16 float4
    if (idx < NN) g_cnt[idx] = 0;
    if (idx >= NN * 16) return;
    float4 v = (idx < NU * 16) ? ((const float4*)ue)[idx]
                               : ((const float4*)ee)[idx - NU * 16];
    ((float4*)g_feats0)[idx] = v;
}

// ---------------------------------------------------------------------------
// CSR build: histogram -> 3-phase exclusive scan -> fill
// ---------------------------------------------------------------------------
__global__ __launch_bounds__(256) void hist_kernel(const int* __restrict__ er)
{
    int e = blockIdx.x * 256 + threadIdx.x;
    if (e < NEDGE) atomicAdd(&g_cnt[er[e]], 1);
}

__global__ __launch_bounds__(SCAN_ELEMS) void scan1_kernel()
{
    __shared__ int s[SCAN_ELEMS];
    int i = blockIdx.x * SCAN_ELEMS + threadIdx.x;
    int v = (i < NN) ? g_cnt[i] : 0;
    s[threadIdx.x] = v;
    __syncthreads();
    #pragma unroll
    for (int off = 1; off < SCAN_ELEMS; off <<= 1) {
        int t = (threadIdx.x >= off) ? s[threadIdx.x - off] : 0;
        __syncthreads();
        s[threadIdx.x] += t;
        __syncthreads();
    }
    if (i < NN) g_rowptr[i] = s[threadIdx.x] - v;        // exclusive within block
    if (threadIdx.x == SCAN_ELEMS - 1) g_bsum[blockIdx.x] = s[SCAN_ELEMS - 1];
}

__global__ __launch_bounds__(256) void scan2_kernel()
{
    __shared__ int s[256];
    int v = (threadIdx.x < NBLK_SCAN) ? g_bsum[threadIdx.x] : 0;
    s[threadIdx.x] = v;
    __syncthreads();
    #pragma unroll
    for (int off = 1; off < 256; off <<= 1) {
        int t = (threadIdx.x >= off) ? s[threadIdx.x - off] : 0;
        __syncthreads();
        s[threadIdx.x] += t;
        __syncthreads();
    }
    g_boff[threadIdx.x] = s[threadIdx.x] - v;            // exclusive
}

__global__ __launch_bounds__(256) void scan3_kernel()
{
    int i = blockIdx.x * 256 + threadIdx.x;
    if (i < NN) {
        int rp = g_rowptr[i] + g_boff[i / SCAN_ELEMS];
        g_rowptr[i] = rp;
        g_cursor[i] = rp;
    }
    if (i == 0) g_rowptr[NN] = NEDGE;
}

__global__ __launch_bounds__(256) void fill_kernel(
    const int* __restrict__ er, const int* __restrict__ ec,
    const float* __restrict__ ev)
{
    int e = blockIdx.x * 256 + threadIdx.x;
    if (e >= NEDGE) return;
    int row = er[e];
    int pos = atomicAdd(&g_cursor[row], 1);
    g_ecv[pos] = make_int2(ec[e], __float_as_int(ev[e]));
}

// ---------------------------------------------------------------------------
// Fused layer kernel: pull-mode SpMM gather into shared Xs/Ys, then dense
// GEMM + leaky_relu + L2 normalize.
// Block = 64 rows, 512 threads, 3 CTAs/SM.
// Gather: DYNAMIC row scheduling via smem ticket counter (load balance);
// per-edge body identical to validated optimum (2x LDG.32 per edge,
// unroll 4, uniform ecv load).
// ---------------------------------------------------------------------------
template<int DOUT, int LAYER>
__global__ __launch_bounds__(512, 3) void layer_fused_kernel(
    const float* __restrict__ W1, const float* __restrict__ b1,
    const float* __restrict__ W2, const float* __restrict__ b2)
{
    const float* __restrict__ feats = (LAYER == 0) ? g_feats0 : g_a1;
    float*       out                = (LAYER == 0) ? g_a1     : g_a2;

    extern __shared__ float sm[];
    float* Xs  = sm;                    // [64][65], k-major: Xs[k*65 + node]
    float* Ys  = Xs + 64 * 65;          // [64][65]
    float* W1s = Ys + 64 * 65;          // [64*DOUT]
    float* W2s = W1s + 64 * DOUT;       // [64*DOUT]
    float* Bs  = W2s + 64 * DOUT;       // [DOUT]
    __shared__ int rowctr;

    const int tid  = threadIdx.x;
    const int r0   = blockIdx.x * 64;
    const int lane = tid & 31;

    if (tid == 0) rowctr = 0;

    // ---- stage W (float4) and bias sum ----
    for (int idx = tid; idx < 64 * DOUT / 4; idx += 512) {
        ((float4*)W1s)[idx] = ((const float4*)W1)[idx];
        ((float4*)W2s)[idx] = ((const float4*)W2)[idx];
    }
    if (tid < DOUT) Bs[tid] = b1[tid] + b2[tid];
    __syncthreads();                    // rowctr visible; W not yet needed

    // ---- pull-mode gather: dynamic row assignment, h in registers ----
    while (true) {
        int rl = 0;
        if (lane == 0) rl = atomicAdd(&rowctr, 1);
        rl = __shfl_sync(0xFFFFFFFFu, rl, 0);
        if (rl >= 64) break;
        int gr = r0 + rl;
        float f0 = 0.f, f1 = 0.f, h0 = 0.f, h1 = 0.f;
        if (gr < NN) {
            f0 = feats[gr * 64 + lane];
            f1 = feats[gr * 64 + 32 + lane];
            int beg = g_rowptr[gr];
            int end = g_rowptr[gr + 1];
            #pragma unroll 4
            for (int e = beg; e < end; e++) {
                int2 cv = g_ecv[e];                 // same addr warp-wide
                float v = __int_as_float(cv.y);
                const float* fp = feats + (size_t)cv.x * 64;
                h0 += fp[lane] * v;
                h1 += fp[32 + lane] * v;
            }
        }
        Xs[lane * 65 + rl]        = f0 + h0;
        Xs[(lane + 32) * 65 + rl] = f1 + h1;
        Ys[lane * 65 + rl]        = f0 * h0;
        Ys[(lane + 32) * 65 + rl] = f1 * h1;
    }
    __syncthreads();

    // ---- dense GEMM: thread (tx,ty) -> 2 nodes x JT outputs ----
    constexpr int JT = DOUT / 16;       // 4 (layer0) or 2 (layer1)
    const int tx = tid & 15;
    const int ty = tid >> 4;            // 0..31

    float acc[2][JT];
    #pragma unroll
    for (int i = 0; i < 2; i++)
        #pragma unroll
        for (int j = 0; j < JT; j++)
            acc[i][j] = Bs[tx * JT + j];

    for (int k = 0; k < 64; k++) {
        float x[2], y[2];
        #pragma unroll
        for (int i = 0; i < 2; i++) {
            x[i] = Xs[k * 65 + ty * 2 + i];
            y[i] = Ys[k * 65 + ty * 2 + i];
        }
        float w1[JT], w2[JT];
        if constexpr (JT == 4) {
            float4 a = *(const float4*)&W1s[k * DOUT + tx * 4];
            float4 b = *(const float4*)&W2s[k * DOUT + tx * 4];
            w1[0] = a.x; w1[1] = a.y; w1[2] = a.z; w1[3] = a.w;
            w2[0] = b.x; w2[1] = b.y; w2[2] = b.z; w2[3] = b.w;
        } else {
            float2 a = *(const float2*)&W1s[k * DOUT + tx * 2];
            float2 b = *(const float2*)&W2s[k * DOUT + tx * 2];
            w1[0] = a.x; w1[1] = a.y;
            w2[0] = b.x; w2[1] = b.y;
        }
        #pragma unroll
        for (int i = 0; i < 2; i++)
            #pragma unroll
            for (int j = 0; j < JT; j++)
                acc[i][j] += x[i] * w1[j] + y[i] * w2[j];
    }

    // ---- epilogue: leaky_relu + L2 normalize (width-16 shfl reduction) ----
    #pragma unroll
    for (int i = 0; i < 2; i++) {
        float p = 0.f;
        #pragma unroll
        for (int j = 0; j < JT; j++) {
            float v = acc[i][j];
            v = (v > 0.f) ? v : 0.01f * v;
            acc[i][j] = v;
            p += v * v;
        }
        p += __shfl_xor_sync(0xFFFFFFFFu, p, 1, 16);
        p += __shfl_xor_sync(0xFFFFFFFFu, p, 2, 16);
        p += __shfl_xor_sync(0xFFFFFFFFu, p, 4, 16);
        p += __shfl_xor_sync(0xFFFFFFFFu, p, 8, 16);
        float inv = 1.f / fmaxf(sqrtf(p), 1e-12f);
        int gr = r0 + ty * 2 + i;
        if (gr < NN) {
            if constexpr (JT == 4) {
                float4 o = make_float4(acc[i][0] * inv, acc[i][1] * inv,
                                       acc[i][2] * inv, acc[i][3] * inv);
                ((float4*)out)[gr * (DOUT / 4) + tx] = o;
            } else {
                float2 o = make_float2(acc[i][0] * inv, acc[i][1] * inv);
                ((float2*)out)[gr * (DOUT / 2) + tx] = o;
            }
        }
    }
}

// ---------------------------------------------------------------------------
// Scoring — warp per pair, dot over concat(a0[64], a1[64], a2[32]).
// ---------------------------------------------------------------------------
__global__ __launch_bounds__(256) void score_kernel(
    const int* __restrict__ uids, const int* __restrict__ iids,
    float* __restrict__ out)
{
    int w = (blockIdx.x * 256 + threadIdx.x) >> 5;
    int l = threadIdx.x & 31;
    if (w >= NB) return;
    int u  = uids[w];
    int it = NU + iids[w];

    const float* fu = g_feats0 + u  * 64;
    const float* fi = g_feats0 + it * 64;
    float s = fu[l] * fi[l] + fu[l + 32] * fi[l + 32];
    const float* au = g_a1 + u  * 64;
    const float* ai = g_a1 + it * 64;
    s += au[l] * ai[l] + au[l + 32] * ai[l + 32];
    s += g_a2[u * 32 + l] * g_a2[it * 32 + l];

    s += __shfl_xor_sync(0xFFFFFFFFu, s, 16);
    s += __shfl_xor_sync(0xFFFFFFFFu, s, 8);
    s += __shfl_xor_sync(0xFFFFFFFFu, s, 4);
    s += __shfl_xor_sync(0xFFFFFFFFu, s, 2);
    s += __shfl_xor_sync(0xFFFFFFFFu, s, 1);
    if (l == 0) out[w] = s;
}

// ---------------------------------------------------------------------------
extern "C" void kernel_launch(void* const* d_in, const int* in_sizes, int n_in,
                              void* d_out, int out_size)
{
    const int*   er   = (const int*)  d_in[0];
    const int*   ec   = (const int*)  d_in[1];
    const float* ev   = (const float*)d_in[2];
    const float* ue   = (const float*)d_in[3];
    const float* ee   = (const float*)d_in[4];
    const float* W1_0 = (const float*)d_in[5];
    const float* b1_0 = (const float*)d_in[6];
    const float* W2_0 = (const float*)d_in[7];
    const float* b2_0 = (const float*)d_in[8];
    const float* W1_1 = (const float*)d_in[9];
    const float* b1_1 = (const float*)d_in[10];
    const float* W2_1 = (const float*)d_in[11];
    const float* b2_1 = (const float*)d_in[12];
    const int*   uids = (const int*)  d_in[13];
    const int*   iids = (const int*)  d_in[14];
    float*       out  = (float*)d_out;

    const size_t smem64 = (size_t)(64 * 65 * 2 + 64 * 64 * 2 + 64) * sizeof(float);
    const size_t smem32 = (size_t)(64 * 65 * 2 + 64 * 32 * 2 + 32) * sizeof(float);
    cudaFuncSetAttribute(layer_fused_kernel<64, 0>,
                         cudaFuncAttributeMaxDynamicSharedMemorySize, (int)smem64);
    cudaFuncSetAttribute(layer_fused_kernel<32, 1>,
                         cudaFuncAttributeMaxDynamicSharedMemorySize, (int)smem32);

    const int layer_blocks = (NN + 63) / 64;
    const int eblocks = (NEDGE + 255) / 256;

    concat_kernel<<<(NN * 16 + 255) / 256, 256>>>(ue, ee);   // also zeros g_cnt
    // CSR build
    hist_kernel<<<eblocks, 256>>>(er);
    scan1_kernel<<<NBLK_SCAN, SCAN_ELEMS>>>();
    scan2_kernel<<<1, 256>>>();
    scan3_kernel<<<(NN + 255) / 256, 256>>>();
    fill_kernel<<<eblocks, 256>>>(er, ec, ev);
    // Fused layers
    layer_fused_kernel<64, 0><<<layer_blocks, 512, smem64>>>(W1_0, b1_0, W2_0, b2_0);
    layer_fused_kernel<32, 1><<<layer_blocks, 512, smem32>>>(W1_1, b1_1, W2_1, b2_1);
    score_kernel<<<(NB * 32) / 256, 256>>>(uids, iids, out);
}

// round 16
// speedup vs baseline: 1.0267x; 1.0165x over previous
#include <cuda_runtime.h>

// Problem constants (match reference_code)
#define NU    30000
#define NENT  70000
#define NN    100000          // NU + NENT
#define NEDGE 1600000
#define NB    4096

#define SCAN_T  512
#define NBLK    ((NN + SCAN_T - 1) / SCAN_T)   // 196

// Scratch (device globals: allocation-free rule).
__device__ float g_feats0[NN * 64];
__device__ float g_a1[NN * 64];
__device__ float g_a2[NN * 32];
// CSR scratch.  g_cnt/g_part zero-invariant: zero in .bss at load, re-zeroed
// by score_kernel at the end of every launch (graph-replay safe).
__device__ int   g_cnt[NN];
__device__ int   g_rowptr[NN + 1];
__device__ int   g_cursor[NN];
__device__ int   g_part[NBLK];
__device__ int2  g_ecv[NEDGE];       // x = col, y = float bits of val

// ---------------------------------------------------------------------------
// K0: concat a0 = [user_embed; entity_embed] (float4) + row histogram.
// NN*16 == NEDGE == 1,600,000 -> one 6250-block grid covers both tasks.
// ---------------------------------------------------------------------------
__global__ __launch_bounds__(256) void concat_hist_kernel(
    const float* __restrict__ ue, const float* __restrict__ ee,
    const int* __restrict__ er)
{
    int idx = blockIdx.x * 256 + threadIdx.x;
    if (idx < NN * 16) {
        float4 v = (idx < NU * 16) ? ((const float4*)ue)[idx]
                                   : ((const float4*)ee)[idx - NU * 16];
        ((float4*)g_feats0)[idx] = v;
    }
    if (idx < NEDGE) atomicAdd(&g_cnt[er[idx]], 1);
}

// ---------------------------------------------------------------------------
// K1: single-pass exclusive scan (decoupled lookback). All NBLK=196 blocks
// resident in one wave -> lookback cannot deadlock. Writes rowptr + cursor.
// ---------------------------------------------------------------------------
__global__ __launch_bounds__(SCAN_T) void scan_kernel()
{
    __shared__ int wsum[16];
    __shared__ int sh_prefix;
    const int tid  = threadIdx.x;
    const int lane = tid & 31;
    const int wp   = tid >> 5;
    const int b    = blockIdx.x;
    const int i    = b * SCAN_T + tid;

    int v = (i < NN) ? g_cnt[i] : 0;
    int s = v;
    #pragma unroll
    for (int off = 1; off < 32; off <<= 1) {
        int t = __shfl_up_sync(0xFFFFFFFFu, s, off);
        if (lane >= off) s += t;
    }
    if (lane == 31) wsum[wp] = s;
    __syncthreads();
    if (wp == 0) {
        int ws = (lane < 16) ? wsum[lane] : 0;
        #pragma unroll
        for (int off = 1; off < 16; off <<= 1) {
            int t = __shfl_up_sync(0xFFFFFFFFu, ws, off);
            if (lane >= off) ws += t;
        }
        if (lane < 16) wsum[lane] = ws;           // inclusive warp sums
    }
    __syncthreads();
    int base  = (wp > 0) ? wsum[wp - 1] : 0;
    int incl  = base + s;                         // inclusive within block
    int total = wsum[15];

    if (tid == 0) {
        if (b == 0) {
            atomicExch(&g_part[0], (2 << 28) | total);
            sh_prefix = 0;
        } else {
            atomicExch(&g_part[b], (1 << 28) | total);
            int run = 0, j = b - 1;
            while (true) {
                int p = atomicAdd(&g_part[j], 0);
                int st = p >> 28;
                if (st == 0) continue;
                run += p & 0x0FFFFFFF;
                if (st == 2) break;
                j--;
            }
            atomicExch(&g_part[b], (2 << 28) | (run + total));
            sh_prefix = run;
        }
    }
    __syncthreads();
    int rp = sh_prefix + incl - v;                // exclusive global prefix
    if (i < NN) { g_rowptr[i] = rp; g_cursor[i] = rp; }
    if (i == NN) g_rowptr[NN] = NEDGE;
    if (b == NBLK - 1 && tid == 0) g_rowptr[NN] = NEDGE;
}

// ---------------------------------------------------------------------------
// K2: fill CSR adjacency (col, val) packed
// ---------------------------------------------------------------------------
__global__ __launch_bounds__(256) void fill_kernel(
    const int* __restrict__ er, const int* __restrict__ ec,
    const float* __restrict__ ev)
{
    int e = blockIdx.x * 256 + threadIdx.x;
    if (e >= NEDGE) return;
    int row = er[e];
    int pos = atomicAdd(&g_cursor[row], 1);
    g_ecv[pos] = make_int2(ec[e], __float_as_int(ev[e]));
}

// ---------------------------------------------------------------------------
// K3/K4: fused layer (R13 canonical, byte-identical hot code):
// pull-mode gather into shared Xs/Ys, then dense GEMM + leaky_relu + L2 norm.
// Block = 64 rows, 512 threads, 3 CTAs/SM; 2x LDG.32/edge, unroll 4.
// ---------------------------------------------------------------------------
template<int DOUT, int LAYER>
__global__ __launch_bounds__(512, 3) void layer_fused_kernel(
    const float* __restrict__ W1, const float* __restrict__ b1,
    const float* __restrict__ W2, const float* __restrict__ b2)
{
    const float* __restrict__ feats = (LAYER == 0) ? g_feats0 : g_a1;
    float*       out                = (LAYER == 0) ? g_a1     : g_a2;

    extern __shared__ float sm[];
    float* Xs  = sm;                    // [64][65], k-major: Xs[k*65 + node]
    float* Ys  = Xs + 64 * 65;          // [64][65]
    float* W1s = Ys + 64 * 65;          // [64*DOUT]
    float* W2s = W1s + 64 * DOUT;       // [64*DOUT]
    float* Bs  = W2s + 64 * DOUT;       // [DOUT]

    const int tid  = threadIdx.x;
    const int r0   = blockIdx.x * 64;
    const int warp = tid >> 5;
    const int lane = tid & 31;

    // ---- stage W (float4) and bias sum ----
    for (int idx = tid; idx < 64 * DOUT / 4; idx += 512) {
        ((float4*)W1s)[idx] = ((const float4*)W1)[idx];
        ((float4*)W2s)[idx] = ((const float4*)W2)[idx];
    }
    if (tid < DOUT) Bs[tid] = b1[tid] + b2[tid];

    // ---- pull-mode gather: h_neigh accumulated in registers ----
    #pragma unroll 1
    for (int i = 0; i < 4; i++) {
        int rl = warp * 4 + i;
        int gr = r0 + rl;
        float f0 = 0.f, f1 = 0.f, h0 = 0.f, h1 = 0.f;
        if (gr < NN) {
            f0 = feats[gr * 64 + lane];
            f1 = feats[gr * 64 + 32 + lane];
            int beg = g_rowptr[gr];
            int end = g_rowptr[gr + 1];
            #pragma unroll 4
            for (int e = beg; e < end; e++) {
                int2 cv = g_ecv[e];                 // same addr warp-wide
                float v = __int_as_float(cv.y);
                const float* fp = feats + (size_t)cv.x * 64;
                h0 += fp[lane] * v;
                h1 += fp[32 + lane] * v;
            }
        }
        Xs[lane * 65 + rl]        = f0 + h0;
        Xs[(lane + 32) * 65 + rl] = f1 + h1;
        Ys[lane * 65 + rl]        = f0 * h0;
        Ys[(lane + 32) * 65 + rl] = f1 * h1;
    }
    __syncthreads();

    // ---- dense GEMM: thread (tx,ty) -> 2 nodes x JT outputs ----
    constexpr int JT = DOUT / 16;       // 4 (layer0) or 2 (layer1)
    const int tx = tid & 15;
    const int ty = tid >> 4;            // 0..31

    float acc[2][JT];
    #pragma unroll
    for (int i = 0; i < 2; i++)
        #pragma unroll
        for (int j = 0; j < JT; j++)
            acc[i][j] = Bs[tx * JT + j];

    for (int k = 0; k < 64; k++) {
        float x[2], y[2];
        #pragma unroll
        for (int i = 0; i < 2; i++) {
            x[i] = Xs[k * 65 + ty * 2 + i];
            y[i] = Ys[k * 65 + ty * 2 + i];
        }
        float w1[JT], w2[JT];
        if constexpr (JT == 4) {
            float4 a = *(const float4*)&W1s[k * DOUT + tx * 4];
            float4 b = *(const float4*)&W2s[k * DOUT + tx * 4];
            w1[0] = a.x; w1[1] = a.y; w1[2] = a.z; w1[3] = a.w;
            w2[0] = b.x; w2[1] = b.y; w2[2] = b.z; w2[3] = b.w;
        } else {
            float2 a = *(const float2*)&W1s[k * DOUT + tx * 2];
            float2 b = *(const float2*)&W2s[k * DOUT + tx * 2];
            w1[0] = a.x; w1[1] = a.y;
            w2[0] = b.x; w2[1] = b.y;
        }
        #pragma unroll
        for (int i = 0; i < 2; i++)
            #pragma unroll
            for (int j = 0; j < JT; j++)
                acc[i][j] += x[i] * w1[j] + y[i] * w2[j];
    }

    // ---- epilogue: leaky_relu + L2 normalize (width-16 shfl reduction) ----
    #pragma unroll
    for (int i = 0; i < 2; i++) {
        float p = 0.f;
        #pragma unroll
        for (int j = 0; j < JT; j++) {
            float v = acc[i][j];
            v = (v > 0.f) ? v : 0.01f * v;
            acc[i][j] = v;
            p += v * v;
        }
        p += __shfl_xor_sync(0xFFFFFFFFu, p, 1, 16);
        p += __shfl_xor_sync(0xFFFFFFFFu, p, 2, 16);
        p += __shfl_xor_sync(0xFFFFFFFFu, p, 4, 16);
        p += __shfl_xor_sync(0xFFFFFFFFu, p, 8, 16);
        float inv = 1.f / fmaxf(sqrtf(p), 1e-12f);
        int gr = r0 + ty * 2 + i;
        if (gr < NN) {
            if constexpr (JT == 4) {
                float4 o = make_float4(acc[i][0] * inv, acc[i][1] * inv,
                                       acc[i][2] * inv, acc[i][3] * inv);
                ((float4*)out)[gr * (DOUT / 4) + tx] = o;
            } else {
                float2 o = make_float2(acc[i][0] * inv, acc[i][1] * inv);
                ((float2*)out)[gr * (DOUT / 2) + tx] = o;
            }
        }
    }
}

// ---------------------------------------------------------------------------
// K5: scoring — warp per pair, dot over concat(a0[64], a1[64], a2[32]).
// Also re-zeroes g_cnt / g_part for the next launch (zero-invariant).
// ---------------------------------------------------------------------------
__global__ __launch_bounds__(256) void score_kernel(
    const int* __restrict__ uids, const int* __restrict__ iids,
    float* __restrict__ out)
{
    int gid = blockIdx.x * 256 + threadIdx.x;
    if (gid < NN) g_cnt[gid] = 0;                 // 512 blocks * 256 = 131072 >= NN
    if (gid < NBLK) g_part[gid] = 0;

    int w = gid >> 5;
    int l = gid & 31;
    if (w >= NB) return;
    int u  = uids[w];
    int it = NU + iids[w];

    const float* fu = g_feats0 + u  * 64;
    const float* fi = g_feats0 + it * 64;
    float s = fu[l] * fi[l] + fu[l + 32] * fi[l + 32];
    const float* au = g_a1 + u  * 64;
    const float* ai = g_a1 + it * 64;
    s += au[l] * ai[l] + au[l + 32] * ai[l + 32];
    s += g_a2[u * 32 + l] * g_a2[it * 32 + l];

    s += __shfl_xor_sync(0xFFFFFFFFu, s, 16);
    s += __shfl_xor_sync(0xFFFFFFFFu, s, 8);
    s += __shfl_xor_sync(0xFFFFFFFFu, s, 4);
    s += __shfl_xor_sync(0xFFFFFFFFu, s, 2);
    s += __shfl_xor_sync(0xFFFFFFFFu, s, 1);
    if (l == 0) out[w] = s;
}

// ---------------------------------------------------------------------------
extern "C" void kernel_launch(void* const* d_in, const int* in_sizes, int n_in,
                              void* d_out, int out_size)
{
    const int*   er   = (const int*)  d_in[0];
    const int*   ec   = (const int*)  d_in[1];
    const float* ev   = (const float*)d_in[2];
    const float* ue   = (const float*)d_in[3];
    const float* ee   = (const float*)d_in[4];
    const float* W1_0 = (const float*)d_in[5];
    const float* b1_0 = (const float*)d_in[6];
    const float* W2_0 = (const float*)d_in[7];
    const float* b2_0 = (const float*)d_in[8];
    const float* W1_1 = (const float*)d_in[9];
    const float* b1_1 = (const float*)d_in[10];
    const float* W2_1 = (const float*)d_in[11];
    const float* b2_1 = (const float*)d_in[12];
    const int*   uids = (const int*)  d_in[13];
    const int*   iids = (const int*)  d_in[14];
    float*       out  = (float*)d_out;

    const size_t smem64 = (size_t)(64 * 65 * 2 + 64 * 64 * 2 + 64) * sizeof(float);
    const size_t smem32 = (size_t)(64 * 65 * 2 + 64 * 32 * 2 + 32) * sizeof(float);
    cudaFuncSetAttribute(layer_fused_kernel<64, 0>,
                         cudaFuncAttributeMaxDynamicSharedMemorySize, (int)smem64);
    cudaFuncSetAttribute(layer_fused_kernel<32, 1>,
                         cudaFuncAttributeMaxDynamicSharedMemorySize, (int)smem32);

    const int layer_blocks = (NN + 63) / 64;
    const int eblocks = (NEDGE + 255) / 256;    // 6250 == NN*16/256

    concat_hist_kernel<<<eblocks, 256>>>(ue, ee, er);                  // 0
    scan_kernel<<<NBLK, SCAN_T>>>();                                   // 1
    fill_kernel<<<eblocks, 256>>>(er, ec, ev);                         // 2
    layer_fused_kernel<64, 0><<<layer_blocks, 512, smem64>>>(W1_0, b1_0, W2_0, b2_0); // 3 (ncu)
    layer_fused_kernel<32, 1><<<layer_blocks, 512, smem32>>>(W1_1, b1_1, W2_1, b2_1); // 4
    score_kernel<<<(NB * 32) / 256, 256>>>(uids, iids, out);           // 5
}

// round 17
// speedup vs baseline: 1.0598x; 1.0323x over previous
#include <cuda_runtime.h>

// Problem constants (match reference_code)
#define NU    30000
#define NENT  70000
#define NN    100000          // NU + NENT
#define NEDGE 1600000
#define NB    4096

#define SCAN_T  512
#define NBLK    ((NN + SCAN_T - 1) / SCAN_T)   // 196
#define XP      66            // Xs/Ys row stride: 8B-aligned node pairs

// Scratch (device globals: allocation-free rule).
__device__ float g_feats0[NN * 64];
__device__ float g_a1[NN * 64];
__device__ float g_a2[NN * 32];
// CSR scratch.  g_cnt/g_part zero-invariant: zero in .bss at load, re-zeroed
// by score_kernel at the end of every launch (graph-replay safe).
__device__ int   g_cnt[NN];
__device__ int   g_rowptr[NN + 1];
__device__ int   g_cursor[NN];
__device__ int   g_part[NBLK];
__device__ int2  g_ecv[NEDGE];       // x = col, y = float bits of val

// ---------------------------------------------------------------------------
// K0: concat a0 = [user_embed; entity_embed] (float4) + row histogram.
// NN*16 == NEDGE == 1,600,000 -> one 6250-block grid covers both tasks.
// ---------------------------------------------------------------------------
__global__ __launch_bounds__(256) void concat_hist_kernel(
    const float* __restrict__ ue, const float* __restrict__ ee,
    const int* __restrict__ er)
{
    int idx = blockIdx.x * 256 + threadIdx.x;
    if (idx < NN * 16) {
        float4 v = (idx < NU * 16) ? ((const float4*)ue)[idx]
                                   : ((const float4*)ee)[idx - NU * 16];
        ((float4*)g_feats0)[idx] = v;
    }
    if (idx < NEDGE) atomicAdd(&g_cnt[er[idx]], 1);
}

// ---------------------------------------------------------------------------
// K1: single-pass exclusive scan (decoupled lookback). All NBLK=196 blocks
// resident in one wave -> lookback cannot deadlock. Writes rowptr + cursor.
// ---------------------------------------------------------------------------
__global__ __launch_bounds__(SCAN_T) void scan_kernel()
{
    __shared__ int wsum[16];
    __shared__ int sh_prefix;
    const int tid  = threadIdx.x;
    const int lane = tid & 31;
    const int wp   = tid >> 5;
    const int b    = blockIdx.x;
    const int i    = b * SCAN_T + tid;

    int v = (i < NN) ? g_cnt[i] : 0;
    int s = v;
    #pragma unroll
    for (int off = 1; off < 32; off <<= 1) {
        int t = __shfl_up_sync(0xFFFFFFFFu, s, off);
        if (lane >= off) s += t;
    }
    if (lane == 31) wsum[wp] = s;
    __syncthreads();
    if (wp == 0) {
        int ws = (lane < 16) ? wsum[lane] : 0;
        #pragma unroll
        for (int off = 1; off < 16; off <<= 1) {
            int t = __shfl_up_sync(0xFFFFFFFFu, ws, off);
            if (lane >= off) ws += t;
        }
        if (lane < 16) wsum[lane] = ws;           // inclusive warp sums
    }
    __syncthreads();
    int base  = (wp > 0) ? wsum[wp - 1] : 0;
    int incl  = base + s;                         // inclusive within block
    int total = wsum[15];

    if (tid == 0) {
        if (b == 0) {
            atomicExch(&g_part[0], (2 << 28) | total);
            sh_prefix = 0;
        } else {
            atomicExch(&g_part[b], (1 << 28) | total);
            int run = 0, j = b - 1;
            while (true) {
                int p = atomicAdd(&g_part[j], 0);
                int st = p >> 28;
                if (st == 0) continue;
                run += p & 0x0FFFFFFF;
                if (st == 2) break;
                j--;
            }
            atomicExch(&g_part[b], (2 << 28) | (run + total));
            sh_prefix = run;
        }
    }
    __syncthreads();
    int rp = sh_prefix + incl - v;                // exclusive global prefix
    if (i < NN) { g_rowptr[i] = rp; g_cursor[i] = rp; }
    if (b == NBLK - 1 && tid == 0) g_rowptr[NN] = NEDGE;
}

// ---------------------------------------------------------------------------
// K2: fill CSR adjacency (col, val) packed
// ---------------------------------------------------------------------------
__global__ __launch_bounds__(256) void fill_kernel(
    const int* __restrict__ er, const int* __restrict__ ec,
    const float* __restrict__ ev)
{
    int e = blockIdx.x * 256 + threadIdx.x;
    if (e >= NEDGE) return;
    int row = er[e];
    int pos = atomicAdd(&g_cursor[row], 1);
    g_ecv[pos] = make_int2(ec[e], __float_as_int(ev[e]));
}

// ---------------------------------------------------------------------------
// K3/K4: fused layer: pull-mode gather into shared Xs/Ys (k-major, pad 66),
// then dense GEMM (LDS.64 x/y pair loads) + leaky_relu + L2 norm.
// Block = 64 rows, 512 threads, 3 CTAs/SM; 2x LDG.32/edge, unroll 4.
// ---------------------------------------------------------------------------
template<int DOUT, int LAYER>
__global__ __launch_bounds__(512, 3) void layer_fused_kernel(
    const float* __restrict__ W1, const float* __restrict__ b1,
    const float* __restrict__ W2, const float* __restrict__ b2)
{
    const float* __restrict__ feats = (LAYER == 0) ? g_feats0 : g_a1;
    float*       out                = (LAYER == 0) ? g_a1     : g_a2;

    extern __shared__ float sm[];
    float* Xs  = sm;                    // [64 k][XP], k-major: Xs[k*XP + node]
    float* Ys  = Xs + 64 * XP;          // [64 k][XP]
    float* W1s = Ys + 64 * XP;          // [64*DOUT]
    float* W2s = W1s + 64 * DOUT;       // [64*DOUT]
    float* Bs  = W2s + 64 * DOUT;       // [DOUT]

    const int tid  = threadIdx.x;
    const int r0   = blockIdx.x * 64;
    const int warp = tid >> 5;
    const int lane = tid & 31;

    // ---- stage W (float4) and bias sum ----
    for (int idx = tid; idx < 64 * DOUT / 4; idx += 512) {
        ((float4*)W1s)[idx] = ((const float4*)W1)[idx];
        ((float4*)W2s)[idx] = ((const float4*)W2)[idx];
    }
    if (tid < DOUT) Bs[tid] = b1[tid] + b2[tid];

    // ---- pull-mode gather: h_neigh accumulated in registers ----
    #pragma unroll 1
    for (int i = 0; i < 4; i++) {
        int rl = warp * 4 + i;
        int gr = r0 + rl;
        float f0 = 0.f, f1 = 0.f, h0 = 0.f, h1 = 0.f;
        if (gr < NN) {
            f0 = feats[gr * 64 + lane];
            f1 = feats[gr * 64 + 32 + lane];
            int beg = g_rowptr[gr];
            int end = g_rowptr[gr + 1];
            #pragma unroll 4
            for (int e = beg; e < end; e++) {
                int2 cv = g_ecv[e];                 // same addr warp-wide
                float v = __int_as_float(cv.y);
                const float* fp = feats + (size_t)cv.x * 64;
                h0 += fp[lane] * v;
                h1 += fp[32 + lane] * v;
            }
        }
        Xs[lane * XP + rl]        = f0 + h0;
        Xs[(lane + 32) * XP + rl] = f1 + h1;
        Ys[lane * XP + rl]        = f0 * h0;
        Ys[(lane + 32) * XP + rl] = f1 * h1;
    }
    __syncthreads();

    // ---- dense GEMM: thread (tx,ty) -> 2 nodes x JT outputs ----
    constexpr int JT = DOUT / 16;       // 4 (layer0) or 2 (layer1)
    const int tx = tid & 15;
    const int ty = tid >> 4;            // 0..31

    float acc[2][JT];
    #pragma unroll
    for (int i = 0; i < 2; i++)
        #pragma unroll
        for (int j = 0; j < JT; j++)
            acc[i][j] = Bs[tx * JT + j];

    for (int k = 0; k < 64; k++) {
        float2 xp = *(const float2*)&Xs[k * XP + ty * 2];   // LDS.64
        float2 yp = *(const float2*)&Ys[k * XP + ty * 2];   // LDS.64
        float x[2], y[2];
        x[0] = xp.x; x[1] = xp.y;
        y[0] = yp.x; y[1] = yp.y;
        float w1[JT], w2[JT];
        if constexpr (JT == 4) {
            float4 a = *(const float4*)&W1s[k * DOUT + tx * 4];
            float4 b = *(const float4*)&W2s[k * DOUT + tx * 4];
            w1[0] = a.x; w1[1] = a.y; w1[2] = a.z; w1[3] = a.w;
            w2[0] = b.x; w2[1] = b.y; w2[2] = b.z; w2[3] = b.w;
        } else {
            float2 a = *(const float2*)&W1s[k * DOUT + tx * 2];
            float2 b = *(const float2*)&W2s[k * DOUT + tx * 2];
            w1[0] = a.x; w1[1] = a.y;
            w2[0] = b.x; w2[1] = b.y;
        }
        #pragma unroll
        for (int i = 0; i < 2; i++)
            #pragma unroll
            for (int j = 0; j < JT; j++)
                acc[i][j] += x[i] * w1[j] + y[i] * w2[j];
    }

    // ---- epilogue: leaky_relu + L2 normalize (width-16 shfl reduction) ----
    #pragma unroll
    for (int i = 0; i < 2; i++) {
        float p = 0.f;
        #pragma unroll
        for (int j = 0; j < JT; j++) {
            float v = acc[i][j];
            v = (v > 0.f) ? v : 0.01f * v;
            acc[i][j] = v;
            p += v * v;
        }
        p += __shfl_xor_sync(0xFFFFFFFFu, p, 1, 16);
        p += __shfl_xor_sync(0xFFFFFFFFu, p, 2, 16);
        p += __shfl_xor_sync(0xFFFFFFFFu, p, 4, 16);
        p += __shfl_xor_sync(0xFFFFFFFFu, p, 8, 16);
        float inv = 1.f / fmaxf(sqrtf(p), 1e-12f);
        int gr = r0 + ty * 2 + i;
        if (gr < NN) {
            if constexpr (JT == 4) {
                float4 o = make_float4(acc[i][0] * inv, acc[i][1] * inv,
                                       acc[i][2] * inv, acc[i][3] * inv);
                ((float4*)out)[gr * (DOUT / 4) + tx] = o;
            } else {
                float2 o = make_float2(acc[i][0] * inv, acc[i][1] * inv);
                ((float2*)out)[gr * (DOUT / 2) + tx] = o;
            }
        }
    }
}

// ---------------------------------------------------------------------------
// K5: scoring — warp per pair, dot over concat(a0[64], a1[64], a2[32]).
// Also re-zeroes g_cnt / g_part for the next launch (zero-invariant).
// ---------------------------------------------------------------------------
__global__ __launch_bounds__(256) void score_kernel(
    const int* __restrict__ uids, const int* __restrict__ iids,
    float* __restrict__ out)
{
    int gid = blockIdx.x * 256 + threadIdx.x;
    if (gid < NN) g_cnt[gid] = 0;                 // 512 blocks * 256 = 131072 >= NN
    if (gid < NBLK) g_part[gid] = 0;

    int w = gid >> 5;
    int l = gid & 31;
    if (w >= NB) return;
    int u  = uids[w];
    int it = NU + iids[w];

    const float* fu = g_feats0 + u  * 64;
    const float* fi = g_feats0 + it * 64;
    float s = fu[l] * fi[l] + fu[l + 32] * fi[l + 32];
    const float* au = g_a1 + u  * 64;
    const float* ai = g_a1 + it * 64;
    s += au[l] * ai[l] + au[l + 32] * ai[l + 32];
    s += g_a2[u * 32 + l] * g_a2[it * 32 + l];

    s += __shfl_xor_sync(0xFFFFFFFFu, s, 16);
    s += __shfl_xor_sync(0xFFFFFFFFu, s, 8);
    s += __shfl_xor_sync(0xFFFFFFFFu, s, 4);
    s += __shfl_xor_sync(0xFFFFFFFFu, s, 2);
    s += __shfl_xor_sync(0xFFFFFFFFu, s, 1);
    if (l == 0) out[w] = s;
}

// ---------------------------------------------------------------------------
extern "C" void kernel_launch(void* const* d_in, const int* in_sizes, int n_in,
                              void* d_out, int out_size)
{
    const int*   er   = (const int*)  d_in[0];
    const int*   ec   = (const int*)  d_in[1];
    const float* ev   = (const float*)d_in[2];
    const float* ue   = (const float*)d_in[3];
    const float* ee   = (const float*)d_in[4];
    const float* W1_0 = (const float*)d_in[5];
    const float* b1_0 = (const float*)d_in[6];
    const float* W2_0 = (const float*)d_in[7];
    const float* b2_0 = (const float*)d_in[8];
    const float* W1_1 = (const float*)d_in[9];
    const float* b1_1 = (const float*)d_in[10];
    const float* W2_1 = (const float*)d_in[11];
    const float* b2_1 = (const float*)d_in[12];
    const int*   uids = (const int*)  d_in[13];
    const int*   iids = (const int*)  d_in[14];
    float*       out  = (float*)d_out;

    const size_t smem64 = (size_t)(64 * XP * 2 + 64 * 64 * 2 + 64) * sizeof(float); // 66816 B
    const size_t smem32 = (size_t)(64 * XP * 2 + 64 * 32 * 2 + 32) * sizeof(float); // 50304 B
    cudaFuncSetAttribute(layer_fused_kernel<64, 0>,
                         cudaFuncAttributeMaxDynamicSharedMemorySize, (int)smem64);
    cudaFuncSetAttribute(layer_fused_kernel<32, 1>,
                         cudaFuncAttributeMaxDynamicSharedMemorySize, (int)smem32);

    const int layer_blocks = (NN + 63) / 64;
    const int eblocks = (NEDGE + 255) / 256;    // 6250 == NN*16/256

    concat_hist_kernel<<<eblocks, 256>>>(ue, ee, er);                  // 0
    scan_kernel<<<NBLK, SCAN_T>>>();                                   // 1
    fill_kernel<<<eblocks, 256>>>(er, ec, ev);                         // 2
    layer_fused_kernel<64, 0><<<layer_blocks, 512, smem64>>>(W1_0, b1_0, W2_0, b2_0); // 3 (ncu)
    layer_fused_kernel<32, 1><<<layer_blocks, 512, smem32>>>(W1_1, b1_1, W2_1, b2_1); // 4
    score_kernel<<<(NB * 32) / 256, 256>>>(uids, iids, out);           // 5
}